// round 14
// baseline (speedup 1.0000x reference)
#include <cuda_runtime.h>
#include <cuda_bf16.h>
#include <math.h>
#include <stdint.h>

#define B_  4
#define S_  2048
#define D_  1024
#define H_  16
#define DH  128
#define M_  (B_*S_)

// ---------------- scratch (device globals) ----------------
__device__ alignas(16) __nv_bfloat16 g_qh[(size_t)B_*H_*S_*DH];  // [bh][s][d] (x0.125)
__device__ alignas(16) __nv_bfloat16 g_ql[(size_t)B_*H_*S_*DH];
__device__ alignas(16) __nv_bfloat16 g_kh[(size_t)B_*H_*S_*DH];  // [bh][s][d]
__device__ alignas(16) __nv_bfloat16 g_kl[(size_t)B_*H_*S_*DH];
__device__ alignas(16) __nv_bfloat16 g_vth[(size_t)B_*H_*DH*S_]; // [bh][d][s]
__device__ alignas(16) __nv_bfloat16 g_vtl[(size_t)B_*H_*DH*S_];

__device__ alignas(16) __nv_bfloat16 g_inh[(size_t)2*M_*D_];
__device__ alignas(16) __nv_bfloat16 g_inl[(size_t)2*M_*D_];
__device__ alignas(16) __nv_bfloat16 g_wth[(size_t)6*D_*D_];
__device__ alignas(16) __nv_bfloat16 g_wtl[(size_t)6*D_*D_];
__device__ alignas(16) __nv_bfloat16 g_wpth[(size_t)D_*2048];
__device__ alignas(16) __nv_bfloat16 g_wptl[(size_t)D_*2048];
__device__ alignas(16) __nv_bfloat16 g_aoh[(size_t)M_*2048];
__device__ alignas(16) __nv_bfloat16 g_aol[(size_t)M_*2048];

#define LD4(p) (*reinterpret_cast<const float4*>(p))

__device__ __forceinline__ uint32_t smem_u32(const void* p) {
    uint32_t a;
    asm("{ .reg .u64 t; cvta.to.shared.u64 t, %1; cvt.u32.u64 %0, t; }" : "=r"(a) : "l"(p));
    return a;
}
#define LDSM4(r, a) \
    asm volatile("ldmatrix.sync.aligned.m8n8.x4.shared.b16 {%0,%1,%2,%3}, [%4];" \
        : "=r"((r)[0]), "=r"((r)[1]), "=r"((r)[2]), "=r"((r)[3]) : "r"(a))
#define MMA16816(d, a, b) \
    asm volatile("mma.sync.aligned.m16n8k16.row.col.f32.bf16.bf16.f32 " \
        "{%0,%1,%2,%3}, {%4,%5,%6,%7}, {%8,%9}, {%0,%1,%2,%3};" \
        : "+f"((d)[0]), "+f"((d)[1]), "+f"((d)[2]), "+f"((d)[3]) \
        : "r"((a)[0]), "r"((a)[1]), "r"((a)[2]), "r"((a)[3]), "r"((b)[0]), "r"((b)[1]))

__device__ __forceinline__ void cp16(uint32_t s, const void* g) {
    asm volatile("cp.async.cg.shared.global [%0], [%1], 16;" :: "r"(s), "l"(g));
}
#define CP_COMMIT() asm volatile("cp.async.commit_group;" ::: "memory")
#define CP_WAIT0()  asm volatile("cp.async.wait_group 0;" ::: "memory")

__device__ __forceinline__ void cvt_hilo(float v, __nv_bfloat16& h, __nv_bfloat16& l) {
    h = __float2bfloat16(v);
    l = __float2bfloat16(v - __bfloat162float(h));
}
__device__ __forceinline__ uint32_t pack_hi2(float a, float b, float& ra, float& rb) {
    __nv_bfloat16 ha = __float2bfloat16(a), hb = __float2bfloat16(b);
    ra = a - __bfloat162float(ha);
    rb = b - __bfloat162float(hb);
    return ((uint32_t)__bfloat16_as_ushort(hb) << 16) | __bfloat16_as_ushort(ha);
}
__device__ __forceinline__ uint32_t pack2(float a, float b) {
    __nv_bfloat16 ha = __float2bfloat16(a), hb = __float2bfloat16(b);
    return ((uint32_t)__bfloat16_as_ushort(hb) << 16) | __bfloat16_as_ushort(ha);
}

// ---------------- pre-pass kernels ----------------
__global__ __launch_bounds__(256)
void conv_in(const float* __restrict__ x, const float* __restrict__ c)
{
    const int side = blockIdx.y;
    const float* src = side ? c : x;
    size_t i4 = (size_t)blockIdx.x * 256 + threadIdx.x;
    float4 v = LD4(src + i4 * 4);
    alignas(8) __nv_bfloat16 hs[4], ls[4];
    cvt_hilo(v.x, hs[0], ls[0]);
    cvt_hilo(v.y, hs[1], ls[1]);
    cvt_hilo(v.z, hs[2], ls[2]);
    cvt_hilo(v.w, hs[3], ls[3]);
    size_t o = (size_t)side * M_ * D_ + i4 * 4;
    *reinterpret_cast<uint2*>(g_inh + o) = *reinterpret_cast<uint2*>(hs);
    *reinterpret_cast<uint2*>(g_inl + o) = *reinterpret_cast<uint2*>(ls);
}

__global__ __launch_bounds__(256)
void transpose_conv6(const float* __restrict__ W0, const float* __restrict__ W1,
                     const float* __restrict__ W2, const float* __restrict__ W3,
                     const float* __restrict__ W4, const float* __restrict__ W5)
{
    __shared__ float t[32][33];
    const int z = blockIdx.z;
    const float* src = (z == 0) ? W0 : (z == 1) ? W1 : (z == 2) ? W2
                     : (z == 3) ? W3 : (z == 4) ? W4 : W5;
    __nv_bfloat16* dsth = g_wth + (size_t)z * D_ * D_;
    __nv_bfloat16* dstl = g_wtl + (size_t)z * D_ * D_;
    int r0 = blockIdx.y * 32, c0 = blockIdx.x * 32;
    int tx = threadIdx.x, ty = threadIdx.y;
    #pragma unroll
    for (int i = 0; i < 32; i += 8)
        t[ty + i][tx] = src[(size_t)(r0 + ty + i) * D_ + c0 + tx];
    __syncthreads();
    #pragma unroll
    for (int i = 0; i < 32; i += 8) {
        float v = t[tx][ty + i];
        __nv_bfloat16 h, l;
        cvt_hilo(v, h, l);
        size_t o = (size_t)(c0 + ty + i) * D_ + r0 + tx;
        dsth[o] = h;
        dstl[o] = l;
    }
}

__global__ __launch_bounds__(256)
void transpose_conv(const float* __restrict__ src, __nv_bfloat16* __restrict__ dsth,
                    __nv_bfloat16* __restrict__ dstl, int R, int C)
{
    __shared__ float t[32][33];
    int r0 = blockIdx.y * 32, c0 = blockIdx.x * 32;
    int tx = threadIdx.x, ty = threadIdx.y;
    #pragma unroll
    for (int i = 0; i < 32; i += 8)
        t[ty + i][tx] = src[(size_t)(r0 + ty + i) * C + c0 + tx];
    __syncthreads();
    #pragma unroll
    for (int i = 0; i < 32; i += 8) {
        float v = t[tx][ty + i];
        __nv_bfloat16 h, l;
        cvt_hilo(v, h, l);
        size_t o = (size_t)(c0 + ty + i) * R + r0 + tx;
        dsth[o] = h;
        dstl[o] = l;
    }
}

// ---------------- split-bf16 MMA GEMM core: CTA 128x128, warp 32x64, BK=64, cp.async ----------------
// stage (bf16 units): Ah[128][72] @0 | Al @9216 | Bh[128][72] @18432 | Bl @27648
#define ASTRIDE2 72
#define STG2_ELE 36864
#define DSMEM_BYTES (2*STG2_ELE*2)   // 147456; Cs [128][129] f32 = 66048 overlays

__device__ __forceinline__ void gemm128_mma(
    const __nv_bfloat16* __restrict__ Agh, const __nv_bfloat16* __restrict__ Agl, int lda,
    const __nv_bfloat16* __restrict__ Bgh, const __nv_bfloat16* __restrict__ Bgl, int ldb,
    int K, __nv_bfloat16* sm, float* Cs)
{
    const int tid = threadIdx.x, lane = tid & 31, wid = tid >> 5;
    const int wm = wid & 3, wn = wid >> 2;
    const uint32_t smb = smem_u32(sm);

    float d[2][8][4];
    #pragma unroll
    for (int i = 0; i < 2; i++)
        #pragma unroll
        for (int j = 0; j < 8; j++)
            #pragma unroll
            for (int q = 0; q < 4; q++) d[i][j][q] = 0.f;

    const int lrow = tid >> 1;            // 0..127
    const int lcol = (tid & 1) * 32;      // 0 or 32 (bf16 units)
    const __nv_bfloat16* pAh = Agh + (size_t)lrow * lda + lcol;
    const __nv_bfloat16* pAl = Agl + (size_t)lrow * lda + lcol;
    const __nv_bfloat16* pBh = Bgh + (size_t)lrow * ldb + lcol;
    const __nv_bfloat16* pBl = Bgl + (size_t)lrow * ldb + lcol;
    const uint32_t sidx = (uint32_t)(lrow * ASTRIDE2 + lcol);

    const int arow = wm * 32 + (lane & 15);
    const int acolL = (lane >> 4) * 8;
    const int brow = wn * 64 + (lane & 7) + ((lane >> 1) & 8);
    const int bcolL = ((lane >> 3) & 1) * 8;

    const int NC = K >> 6;   // 64-deep chunks

    // prologue: chunk 0 -> stage 0 via cp.async (4 cp16 per region, cols +0,+8,+16,+24)
    {
        #pragma unroll
        for (int i = 0; i < 4; i++) {
            cp16(smb + (sidx + i * 8) * 2,          pAh + i * 8);
            cp16(smb + (9216 + sidx + i * 8) * 2,   pAl + i * 8);
            cp16(smb + (18432 + sidx + i * 8) * 2,  pBh + i * 8);
            cp16(smb + (27648 + sidx + i * 8) * 2,  pBl + i * 8);
        }
        CP_COMMIT();
        CP_WAIT0();
    }
    __syncthreads();

    for (int ch = 0; ch < NC; ch++) {
        const int cur = ch & 1;
        const int nxt = cur ^ 1;
        const bool has = (ch + 1 < NC);
        const int k1 = (ch + 1) * 64;

        // issue next chunk into the alternate stage (its readers synced at prior barrier)
        if (has) {
            const uint32_t st = smb + (uint32_t)(nxt * STG2_ELE) * 2;
            #pragma unroll
            for (int i = 0; i < 4; i++) {
                cp16(st + (sidx + i * 8) * 2,         pAh + k1 + i * 8);
                cp16(st + (9216 + sidx + i * 8) * 2,  pAl + k1 + i * 8);
                cp16(st + (18432 + sidx + i * 8) * 2, pBh + k1 + i * 8);
                cp16(st + (27648 + sidx + i * 8) * 2, pBl + k1 + i * 8);
            }
            CP_COMMIT();
        }

        const uint32_t sAh = smb + (uint32_t)(cur * STG2_ELE) * 2;
        const uint32_t sAl = sAh + 9216 * 2;
        const uint32_t sBh = sAh + 18432 * 2;
        const uint32_t sBl = sAh + 27648 * 2;

        #pragma unroll
        for (int k16 = 0; k16 < 4; k16++) {
            const int acol = k16 * 16 + acolL;
            const int bcol = k16 * 16 + bcolL;
            uint32_t aH[2][4], aL[2][4], bH[4][4], bL[4][4];
            LDSM4(aH[0], sAh + (uint32_t)((arow      ) * ASTRIDE2 + acol) * 2);
            LDSM4(aH[1], sAh + (uint32_t)((arow + 16 ) * ASTRIDE2 + acol) * 2);
            LDSM4(aL[0], sAl + (uint32_t)((arow      ) * ASTRIDE2 + acol) * 2);
            LDSM4(aL[1], sAl + (uint32_t)((arow + 16 ) * ASTRIDE2 + acol) * 2);
            #pragma unroll
            for (int nt = 0; nt < 4; nt++) {
                LDSM4(bH[nt], sBh + (uint32_t)((brow + nt * 16) * ASTRIDE2 + bcol) * 2);
                LDSM4(bL[nt], sBl + (uint32_t)((brow + nt * 16) * ASTRIDE2 + bcol) * 2);
            }
            #pragma unroll
            for (int mt = 0; mt < 2; mt++)
                #pragma unroll
                for (int n8 = 0; n8 < 8; n8++) {
                    uint32_t* bh2 = &bH[n8 >> 1][(n8 & 1) * 2];
                    uint32_t* bl2 = &bL[n8 >> 1][(n8 & 1) * 2];
                    MMA16816(d[mt][n8], aH[mt], bh2);
                    MMA16816(d[mt][n8], aH[mt], bl2);
                    MMA16816(d[mt][n8], aL[mt], bh2);
                }
        }
        if (has) { CP_WAIT0(); }
        __syncthreads();   // single barrier per 64-deep chunk
    }

    #pragma unroll
    for (int mt = 0; mt < 2; mt++) {
        const int r0 = wm * 32 + mt * 16 + (lane >> 2);
        #pragma unroll
        for (int n8 = 0; n8 < 8; n8++) {
            const int c0 = wn * 64 + n8 * 8 + (lane & 3) * 2;
            Cs[r0 * 129 + c0]       = d[mt][n8][0];
            Cs[r0 * 129 + c0 + 1]   = d[mt][n8][1];
            Cs[(r0+8) * 129 + c0]   = d[mt][n8][2];
            Cs[(r0+8) * 129 + c0+1] = d[mt][n8][3];
        }
    }
    __syncthreads();
}

// ---------------- projection kernel (tensor cores, bf16 hi/lo outputs) ----------------
__global__ __launch_bounds__(256, 1)
void proj_mma()
{
    extern __shared__ __nv_bfloat16 sm[];
    float* Cs = (float*)sm;
    const int tid = threadIdx.x, lane = tid & 31, wid = tid >> 5;
    const int z = blockIdx.z, side = z / 3, kind = z % 3;
    const int m0 = blockIdx.y * 128, n0 = blockIdx.x * 128;

    const __nv_bfloat16* Ah = g_inh + (size_t)side * M_ * D_ + (size_t)m0 * D_;
    const __nv_bfloat16* Al = g_inl + (size_t)side * M_ * D_ + (size_t)m0 * D_;
    const __nv_bfloat16* Bh = g_wth + (size_t)z * D_ * D_ + (size_t)n0 * D_;
    const __nv_bfloat16* Bl = g_wtl + (size_t)z * D_ * D_ + (size_t)n0 * D_;

    gemm128_mma(Ah, Al, D_, Bh, Bl, D_, D_, sm, Cs);

    const int bq = m0 >> 11;
    const int s0 = m0 & 2047;

    if (kind != 2) {
        __nv_bfloat16* dh = (kind == 0) ? g_qh : g_kh;
        __nv_bfloat16* dl = (kind == 0) ? g_ql : g_kl;
        const float scale = (kind == 0) ? 0.125f : 1.0f;
        #pragma unroll
        for (int rr = 0; rr < 16; rr++) {
            const int row = wid * 16 + rr;
            const int s = s0 + row;
            #pragma unroll
            for (int g = 0; g < 2; g++) {
                const int cl = g * 64 + lane * 2;
                const int n = n0 + cl;
                const int h = n >> 6, dd = (n & 63) + side * 64;
                float v0 = Cs[row * 129 + cl] * scale;
                float v1 = Cs[row * 129 + cl + 1] * scale;
                float r0, r1;
                uint32_t hh = pack_hi2(v0, v1, r0, r1);
                uint32_t ll = pack2(r0, r1);
                size_t o = ((size_t)(bq * H_ + h) * S_ + s) * DH + dd;
                *(uint32_t*)(dh + o) = hh;
                *(uint32_t*)(dl + o) = ll;
            }
        }
    } else {
        #pragma unroll
        for (int cc = 0; cc < 16; cc++) {
            const int col = wid * 16 + cc;
            const int n = n0 + col;
            const int h = n >> 6, dd = (n & 63) + side * 64;
            size_t base = ((size_t)(bq * H_ + h) * DH + dd) * S_ + s0;
            #pragma unroll
            for (int rb = 0; rb < 4; rb++) {
                const int r = rb * 32 + lane;
                float v = Cs[r * 129 + col];
                __nv_bfloat16 hh, ll;
                cvt_hilo(v, hh, ll);
                g_vth[base + r] = hh;
                g_vtl[base + r] = ll;
            }
        }
    }
}

// ---------------- output projection (tensor cores) ----------------
__global__ __launch_bounds__(256, 1)
void outproj_mma(const float* __restrict__ bias, float* __restrict__ out)
{
    extern __shared__ __nv_bfloat16 sm[];
    float* Cs = (float*)sm;
    const int tid = threadIdx.x, lane = tid & 31, wid = tid >> 5;
    const int m0 = blockIdx.y * 128, n0 = blockIdx.x * 128;
    const int K = 2048;

    const __nv_bfloat16* Ah = g_aoh + (size_t)m0 * K;
    const __nv_bfloat16* Al = g_aol + (size_t)m0 * K;
    const __nv_bfloat16* Bh = g_wpth + (size_t)n0 * K;
    const __nv_bfloat16* Bl = g_wptl + (size_t)n0 * K;

    gemm128_mma(Ah, Al, K, Bh, Bl, K, K, sm, Cs);

    #pragma unroll
    for (int rr = 0; rr < 16; rr++) {
        const int row = wid * 16 + rr;
        const size_t gm = (size_t)(m0 + row);
        #pragma unroll
        for (int g = 0; g < 4; g++) {
            const int col = g * 32 + lane;
            out[gm * D_ + n0 + col] = Cs[row * 129 + col] + bias[n0 + col];
        }
    }
}

// ---------------- flash attention with mma.sync (R8 config, best measured) ----------------
#define FQH 0
#define FQL 17408
#define FKH 34816
#define FKL 43520
#define FVH 52224
#define FVL 61440
#define FLASH_ELE 70656
#define FLASH_BYTES (FLASH_ELE*2)
#define NBLK 32

__global__ __launch_bounds__(256, 1)
void flash_mma()
{
    extern __shared__ __nv_bfloat16 fsm[];
    const uint32_t smb = smem_u32(fsm);
    const int tid = threadIdx.x, lane = tid & 31, wid = tid >> 5;
    const int bh = blockIdx.y;
    const int s0 = blockIdx.x * 128;

    const __nv_bfloat16* Qh = g_qh + (size_t)bh * S_ * DH;
    const __nv_bfloat16* Ql = g_ql + (size_t)bh * S_ * DH;
    const __nv_bfloat16* Kh = g_kh + (size_t)bh * S_ * DH;
    const __nv_bfloat16* Kl = g_kl + (size_t)bh * S_ * DH;
    const __nv_bfloat16* Vth = g_vth + (size_t)bh * DH * S_;
    const __nv_bfloat16* Vtl = g_vtl + (size_t)bh * DH * S_;

    {
        const int row = tid >> 1, c = (tid & 1) * 64;
        const __nv_bfloat16* sq = Qh + (size_t)(s0 + row) * DH + c;
        const __nv_bfloat16* sl = Ql + (size_t)(s0 + row) * DH + c;
        __nv_bfloat16* dq = fsm + FQH + row * 136 + c;
        __nv_bfloat16* dl = fsm + FQL + row * 136 + c;
        #pragma unroll
        for (int i = 0; i < 8; i++) {
            *(uint4*)(dq + i * 8) = *(const uint4*)(sq + i * 8);
            *(uint4*)(dl + i * 8) = *(const uint4*)(sl + i * 8);
        }
    }

    float O[16][4];
    #pragma unroll
    for (int i = 0; i < 16; i++)
        #pragma unroll
        for (int q = 0; q < 4; q++) O[i][q] = 0.f;
    float mrow[2] = {-1e30f, -1e30f}, lrow[2] = {0.f, 0.f};

    const int arow = wid * 16 + (lane & 15);
    const int acolL = (lane >> 4) * 8;
    const int brow = (lane & 7) + ((lane >> 1) & 8);
    const int bcolL = ((lane >> 3) & 1) * 8;

    for (int b = 0; b < NBLK; b++) {
        const int j0 = b * 64;

        {
            const int row = tid >> 2, c = (tid & 3) * 32;
            const __nv_bfloat16* sh = Kh + (size_t)(j0 + row) * DH + c;
            const __nv_bfloat16* sl = Kl + (size_t)(j0 + row) * DH + c;
            __nv_bfloat16* dh = fsm + FKH + row * 136 + c;
            __nv_bfloat16* dl = fsm + FKL + row * 136 + c;
            #pragma unroll
            for (int i = 0; i < 4; i++) {
                *(uint4*)(dh + i * 8) = *(const uint4*)(sh + i * 8);
                *(uint4*)(dl + i * 8) = *(const uint4*)(sl + i * 8);
            }
        }
        {
            const int row = tid >> 1, c = (tid & 1) * 32;
            const __nv_bfloat16* vh = Vth + (size_t)row * S_ + j0 + c;
            const __nv_bfloat16* vl = Vtl + (size_t)row * S_ + j0 + c;
            __nv_bfloat16* dh = fsm + FVH + row * 72 + c;
            __nv_bfloat16* dl = fsm + FVL + row * 72 + c;
            #pragma unroll
            for (int i = 0; i < 4; i++) {
                *(uint4*)(dh + i * 8) = *(const uint4*)(vh + i * 8);
                *(uint4*)(dl + i * 8) = *(const uint4*)(vl + i * 8);
            }
        }
        __syncthreads();

        float sv[8][4];
        #pragma unroll
        for (int j = 0; j < 8; j++)
            #pragma unroll
            for (int q = 0; q < 4; q++) sv[j][q] = 0.f;

        const uint32_t kHb = smb + (uint32_t)FKH * 2;
        const uint32_t kLb = smb + (uint32_t)FKL * 2;
        #pragma unroll
        for (int kk = 0; kk < 8; kk++) {
            const int acol = kk * 16 + acolL;
            const int bcol = kk * 16 + bcolL;
            uint32_t aH[4], aL[4], bHf[4][4], bLf[4][4];
            LDSM4(aH, smb + (uint32_t)(FQH + arow * 136 + acol) * 2);
            LDSM4(aL, smb + (uint32_t)(FQL + arow * 136 + acol) * 2);
            #pragma unroll
            for (int nt = 0; nt < 4; nt++) {
                LDSM4(bHf[nt], kHb + (uint32_t)((nt * 16 + brow) * 136 + bcol) * 2);
                LDSM4(bLf[nt], kLb + (uint32_t)((nt * 16 + brow) * 136 + bcol) * 2);
            }
            #pragma unroll
            for (int n8 = 0; n8 < 8; n8++) {
                uint32_t* bh2 = &bHf[n8 >> 1][(n8 & 1) * 2];
                uint32_t* bl2 = &bLf[n8 >> 1][(n8 & 1) * 2];
                MMA16816(sv[n8], aH, bh2);
                MMA16816(sv[n8], aH, bl2);
                MMA16816(sv[n8], aL, bh2);
            }
        }

        float bm0 = sv[0][0], bm1 = sv[0][2];
        #pragma unroll
        for (int j = 0; j < 8; j++) {
            bm0 = fmaxf(bm0, fmaxf(sv[j][0], sv[j][1]));
            bm1 = fmaxf(bm1, fmaxf(sv[j][2], sv[j][3]));
        }
        bm0 = fmaxf(bm0, __shfl_xor_sync(0xffffffffu, bm0, 1));
        bm0 = fmaxf(bm0, __shfl_xor_sync(0xffffffffu, bm0, 2));
        bm1 = fmaxf(bm1, __shfl_xor_sync(0xffffffffu, bm1, 1));
        bm1 = fmaxf(bm1, __shfl_xor_sync(0xffffffffu, bm1, 2));
        const float mn0 = fmaxf(mrow[0], bm0), mn1 = fmaxf(mrow[1], bm1);
        const float corr0 = __expf(mrow[0] - mn0), corr1 = __expf(mrow[1] - mn1);
        float bs0 = 0.f, bs1 = 0.f;
        #pragma unroll
        for (int j = 0; j < 8; j++) {
            sv[j][0] = __expf(sv[j][0] - mn0);
            sv[j][1] = __expf(sv[j][1] - mn0);
            sv[j][2] = __expf(sv[j][2] - mn1);
            sv[j][3] = __expf(sv[j][3] - mn1);
            bs0 += sv[j][0] + sv[j][1];
            bs1 += sv[j][2] + sv[j][3];
        }
        bs0 += __shfl_xor_sync(0xffffffffu, bs0, 1);
        bs0 += __shfl_xor_sync(0xffffffffu, bs0, 2);
        bs1 += __shfl_xor_sync(0xffffffffu, bs1, 1);
        bs1 += __shfl_xor_sync(0xffffffffu, bs1, 2);
        lrow[0] = lrow[0] * corr0 + bs0;
        lrow[1] = lrow[1] * corr1 + bs1;
        mrow[0] = mn0; mrow[1] = mn1;
        #pragma unroll
        for (int i = 0; i < 16; i++) {
            O[i][0] *= corr0; O[i][1] *= corr0;
            O[i][2] *= corr1; O[i][3] *= corr1;
        }

        const uint32_t vHb = smb + (uint32_t)FVH * 2;
        const uint32_t vLb = smb + (uint32_t)FVL * 2;
        #pragma unroll
        for (int c = 0; c < 4; c++) {
            float r0, r1;
            uint32_t pah[4], pal[4];
            pah[0] = pack_hi2(sv[2*c][0],   sv[2*c][1],   r0, r1); pal[0] = pack2(r0, r1);
            pah[1] = pack_hi2(sv[2*c][2],   sv[2*c][3],   r0, r1); pal[1] = pack2(r0, r1);
            pah[2] = pack_hi2(sv[2*c+1][0], sv[2*c+1][1], r0, r1); pal[2] = pack2(r0, r1);
            pah[3] = pack_hi2(sv[2*c+1][2], sv[2*c+1][3], r0, r1); pal[3] = pack2(r0, r1);
            const int bcol = c * 16 + bcolL;
            #pragma unroll
            for (int t = 0; t < 8; t++) {
                uint32_t vh[4], vl[4];
                LDSM4(vh, vHb + (uint32_t)((t * 16 + brow) * 72 + bcol) * 2);
                LDSM4(vl, vLb + (uint32_t)((t * 16 + brow) * 72 + bcol) * 2);
                #pragma unroll
                for (int h2 = 0; h2 < 2; h2++) {
                    uint32_t* vh2 = &vh[h2 * 2];
                    uint32_t* vl2 = &vl[h2 * 2];
                    MMA16816(O[t * 2 + h2], pah, vh2);
                    MMA16816(O[t * 2 + h2], pah, vl2);
                    MMA16816(O[t * 2 + h2], pal, vh2);
                }
            }
        }
        __syncthreads();
    }

    const int b = bh / H_, h = bh % H_;
    const float inv0 = 1.0f / lrow[0], inv1 = 1.0f / lrow[1];
    size_t base0 = (size_t)(b * S_ + s0 + wid * 16 + (lane >> 2)) * 2048 + (size_t)h * 128;
    size_t base1 = base0 + (size_t)8 * 2048;
    #pragma unroll
    for (int n8 = 0; n8 < 16; n8++) {
        const int dv = n8 * 8 + (lane & 3) * 2;
        float v0 = O[n8][0] * inv0, v1 = O[n8][1] * inv0;
        float v2 = O[n8][2] * inv1, v3 = O[n8][3] * inv1;
        float r0, r1;
        uint32_t hh = pack_hi2(v0, v1, r0, r1);
        *(uint32_t*)(g_aoh + base0 + dv) = hh;
        *(uint32_t*)(g_aol + base0 + dv) = pack2(r0, r1);
        hh = pack_hi2(v2, v3, r0, r1);
        *(uint32_t*)(g_aoh + base1 + dv) = hh;
        *(uint32_t*)(g_aol + base1 + dv) = pack2(r0, r1);
    }
}

// =================================================================
extern "C" void kernel_launch(void* const* d_in, const int* in_sizes, int n_in,
                              void* d_out, int out_size)
{
    const float* x    = (const float*)d_in[0];
    const float* c    = (const float*)d_in[1];
    const float* Wp   = (const float*)d_in[8];
    const float* bias = (const float*)d_in[9];
    float* out = (float*)d_out;

    cudaFuncSetAttribute(proj_mma, cudaFuncAttributeMaxDynamicSharedMemorySize, DSMEM_BYTES);
    cudaFuncSetAttribute(outproj_mma, cudaFuncAttributeMaxDynamicSharedMemorySize, DSMEM_BYTES);
    cudaFuncSetAttribute(flash_mma, cudaFuncAttributeMaxDynamicSharedMemorySize, FLASH_BYTES);

    void *p_wpth, *p_wptl;
    cudaGetSymbolAddress(&p_wpth, g_wpth);
    cudaGetSymbolAddress(&p_wptl, g_wptl);

    conv_in<<<dim3(M_*D_/4/256, 2), 256>>>(x, c);
    transpose_conv6<<<dim3(32, 32, 6), dim3(32, 8)>>>(
        (const float*)d_in[2], (const float*)d_in[3], (const float*)d_in[4],
        (const float*)d_in[5], (const float*)d_in[6], (const float*)d_in[7]);
    transpose_conv<<<dim3(32, 64), dim3(32, 8)>>>(
        Wp, (__nv_bfloat16*)p_wpth, (__nv_bfloat16*)p_wptl, 2048, D_);

    proj_mma<<<dim3(8, 64, 6), 256, DSMEM_BYTES>>>();

    flash_mma<<<dim3(S_/128, B_*H_), 256, FLASH_BYTES>>>();

    outproj_mma<<<dim3(8, 64), 256, DSMEM_BYTES>>>(bias, out);
}

// round 15
// speedup vs baseline: 1.1364x; 1.1364x over previous
#include <cuda_runtime.h>
#include <cuda_bf16.h>
#include <math.h>
#include <stdint.h>

#define B_  4
#define S_  2048
#define D_  1024
#define H_  16
#define DH  128
#define M_  (B_*S_)

// ---------------- scratch (device globals) ----------------
__device__ alignas(16) __nv_bfloat16 g_qh[(size_t)B_*H_*S_*DH];  // [bh][s][d] (x0.125*log2e)
__device__ alignas(16) __nv_bfloat16 g_ql[(size_t)B_*H_*S_*DH];
__device__ alignas(16) __nv_bfloat16 g_kh[(size_t)B_*H_*S_*DH];  // [bh][s][d]
__device__ alignas(16) __nv_bfloat16 g_kl[(size_t)B_*H_*S_*DH];
__device__ alignas(16) __nv_bfloat16 g_vth[(size_t)B_*H_*DH*S_]; // [bh][d][s]
__device__ alignas(16) __nv_bfloat16 g_vtl[(size_t)B_*H_*DH*S_];

__device__ alignas(16) __nv_bfloat16 g_inh[(size_t)2*M_*D_];
__device__ alignas(16) __nv_bfloat16 g_inl[(size_t)2*M_*D_];
__device__ alignas(16) __nv_bfloat16 g_wth[(size_t)6*D_*D_];
__device__ alignas(16) __nv_bfloat16 g_wtl[(size_t)6*D_*D_];
__device__ alignas(16) __nv_bfloat16 g_wpth[(size_t)D_*2048];
__device__ alignas(16) __nv_bfloat16 g_wptl[(size_t)D_*2048];
__device__ alignas(16) __nv_bfloat16 g_aoh[(size_t)M_*2048];
__device__ alignas(16) __nv_bfloat16 g_aol[(size_t)M_*2048];

#define LD4(p) (*reinterpret_cast<const float4*>(p))

__device__ __forceinline__ uint32_t smem_u32(const void* p) {
    uint32_t a;
    asm("{ .reg .u64 t; cvta.to.shared.u64 t, %1; cvt.u32.u64 %0, t; }" : "=r"(a) : "l"(p));
    return a;
}
#define LDSM4(r, a) \
    asm volatile("ldmatrix.sync.aligned.m8n8.x4.shared.b16 {%0,%1,%2,%3}, [%4];" \
        : "=r"((r)[0]), "=r"((r)[1]), "=r"((r)[2]), "=r"((r)[3]) : "r"(a))
#define MMA16816(d, a, b) \
    asm volatile("mma.sync.aligned.m16n8k16.row.col.f32.bf16.bf16.f32 " \
        "{%0,%1,%2,%3}, {%4,%5,%6,%7}, {%8,%9}, {%0,%1,%2,%3};" \
        : "+f"((d)[0]), "+f"((d)[1]), "+f"((d)[2]), "+f"((d)[3]) \
        : "r"((a)[0]), "r"((a)[1]), "r"((a)[2]), "r"((a)[3]), "r"((b)[0]), "r"((b)[1]))

__device__ __forceinline__ void cvt_hilo(float v, __nv_bfloat16& h, __nv_bfloat16& l) {
    h = __float2bfloat16(v);
    l = __float2bfloat16(v - __bfloat162float(h));
}
__device__ __forceinline__ uint32_t pack_hi2(float a, float b, float& ra, float& rb) {
    __nv_bfloat16 ha = __float2bfloat16(a), hb = __float2bfloat16(b);
    ra = a - __bfloat162float(ha);
    rb = b - __bfloat162float(hb);
    return ((uint32_t)__bfloat16_as_ushort(hb) << 16) | __bfloat16_as_ushort(ha);
}
__device__ __forceinline__ uint32_t pack2(float a, float b) {
    __nv_bfloat16 ha = __float2bfloat16(a), hb = __float2bfloat16(b);
    return ((uint32_t)__bfloat16_as_ushort(hb) << 16) | __bfloat16_as_ushort(ha);
}

// ---------------- pre-pass kernels ----------------
__global__ __launch_bounds__(256)
void conv_in(const float* __restrict__ x, const float* __restrict__ c)
{
    const int side = blockIdx.y;
    const float* src = side ? c : x;
    size_t i4 = (size_t)blockIdx.x * 256 + threadIdx.x;
    float4 v = LD4(src + i4 * 4);
    alignas(8) __nv_bfloat16 hs[4], ls[4];
    cvt_hilo(v.x, hs[0], ls[0]);
    cvt_hilo(v.y, hs[1], ls[1]);
    cvt_hilo(v.z, hs[2], ls[2]);
    cvt_hilo(v.w, hs[3], ls[3]);
    size_t o = (size_t)side * M_ * D_ + i4 * 4;
    *reinterpret_cast<uint2*>(g_inh + o) = *reinterpret_cast<uint2*>(hs);
    *reinterpret_cast<uint2*>(g_inl + o) = *reinterpret_cast<uint2*>(ls);
}

// transpose+convert the 6 projection weights in one launch (z selects weight)
__global__ __launch_bounds__(256)
void transpose_conv6(const float* __restrict__ W0, const float* __restrict__ W1,
                     const float* __restrict__ W2, const float* __restrict__ W3,
                     const float* __restrict__ W4, const float* __restrict__ W5)
{
    __shared__ float t[32][33];
    const int z = blockIdx.z;
    const float* src = (z == 0) ? W0 : (z == 1) ? W1 : (z == 2) ? W2
                     : (z == 3) ? W3 : (z == 4) ? W4 : W5;
    __nv_bfloat16* dsth = g_wth + (size_t)z * D_ * D_;
    __nv_bfloat16* dstl = g_wtl + (size_t)z * D_ * D_;
    int r0 = blockIdx.y * 32, c0 = blockIdx.x * 32;
    int tx = threadIdx.x, ty = threadIdx.y;
    #pragma unroll
    for (int i = 0; i < 32; i += 8)
        t[ty + i][tx] = src[(size_t)(r0 + ty + i) * D_ + c0 + tx];
    __syncthreads();
    #pragma unroll
    for (int i = 0; i < 32; i += 8) {
        float v = t[tx][ty + i];
        __nv_bfloat16 h, l;
        cvt_hilo(v, h, l);
        size_t o = (size_t)(c0 + ty + i) * D_ + r0 + tx;
        dsth[o] = h;
        dstl[o] = l;
    }
}

__global__ __launch_bounds__(256)
void transpose_conv(const float* __restrict__ src, __nv_bfloat16* __restrict__ dsth,
                    __nv_bfloat16* __restrict__ dstl, int R, int C)
{
    __shared__ float t[32][33];
    int r0 = blockIdx.y * 32, c0 = blockIdx.x * 32;
    int tx = threadIdx.x, ty = threadIdx.y;
    #pragma unroll
    for (int i = 0; i < 32; i += 8)
        t[ty + i][tx] = src[(size_t)(r0 + ty + i) * C + c0 + tx];
    __syncthreads();
    #pragma unroll
    for (int i = 0; i < 32; i += 8) {
        float v = t[tx][ty + i];
        __nv_bfloat16 h, l;
        cvt_hilo(v, h, l);
        size_t o = (size_t)(c0 + ty + i) * R + r0 + tx;
        dsth[o] = h;
        dstl[o] = l;
    }
}

// ---------------- split-bf16 MMA GEMM core, BK=64 per stage (R11, best measured) ----------------
// smem stage (bf16 units): Ah[128][72] @0 | Al @9216 | Bh @18432 | Bl @27648
// Each thread covers one 128-row tile half-row: 32 cols = 4 uint4 per region.
#define ASTRIDE2 72
#define STG2_ELE 36864
#define DSMEM_BYTES (2*STG2_ELE*2)   // 147456; Cs (66048 B) overlays

__device__ __forceinline__ void gemm128_mma(
    const __nv_bfloat16* __restrict__ Agh, const __nv_bfloat16* __restrict__ Agl, int lda,
    const __nv_bfloat16* __restrict__ Bgh, const __nv_bfloat16* __restrict__ Bgl, int ldb,
    int K, __nv_bfloat16* sm, float* Cs)
{
    const int tid = threadIdx.x, lane = tid & 31, wid = tid >> 5;
    const int wm = wid & 3, wn = wid >> 2;
    const uint32_t smb = smem_u32(sm);

    float d[2][8][4];
    #pragma unroll
    for (int i = 0; i < 2; i++)
        #pragma unroll
        for (int j = 0; j < 8; j++)
            #pragma unroll
            for (int q = 0; q < 4; q++) d[i][j][q] = 0.f;

    const int lrow = tid >> 1;            // 0..127
    const int lcol = (tid & 1) * 32;      // 0 or 32 (bf16 units)
    const __nv_bfloat16* pAh = Agh + (size_t)lrow * lda + lcol;
    const __nv_bfloat16* pAl = Agl + (size_t)lrow * lda + lcol;
    const __nv_bfloat16* pBh = Bgh + (size_t)lrow * ldb + lcol;
    const __nv_bfloat16* pBl = Bgl + (size_t)lrow * ldb + lcol;
    const int sidx = lrow * ASTRIDE2 + lcol;

    const int arow = wm * 32 + (lane & 15);
    const int acolL = (lane >> 4) * 8;
    const int brow = wn * 64 + (lane & 7) + ((lane >> 1) & 8);
    const int bcolL = ((lane >> 3) & 1) * 8;

    const int NC = K >> 6;   // 64-deep chunks

    // load chunk 0 into stage 0 (4 uint4 per region: cols +0,+8,+16,+24)
    #pragma unroll
    for (int i = 0; i < 4; i++) {
        *(uint4*)(sm + sidx + i * 8)         = *(const uint4*)(pAh + i * 8);
        *(uint4*)(sm + 9216 + sidx + i * 8)  = *(const uint4*)(pAl + i * 8);
        *(uint4*)(sm + 18432 + sidx + i * 8) = *(const uint4*)(pBh + i * 8);
        *(uint4*)(sm + 27648 + sidx + i * 8) = *(const uint4*)(pBl + i * 8);
    }
    __syncthreads();

    for (int ch = 0; ch < NC; ch++) {
        const int cur = ch & 1;
        const int nxt = cur ^ 1;
        const bool has = (ch + 1 < NC);
        const int k1 = (ch + 1) * 64;

        const uint32_t sAh = smb + (cur * STG2_ELE) * 2;
        const uint32_t sAl = sAh + 9216 * 2;
        const uint32_t sBh = sAh + 18432 * 2;
        const uint32_t sBl = sAh + 27648 * 2;
        __nv_bfloat16* st = sm + nxt * STG2_ELE;

        // ---- A prefetch (regs): Ah + Al, 4 uint4 each ----
        uint4 aP[8];
        if (has) {
            #pragma unroll
            for (int i = 0; i < 4; i++) {
                aP[i]     = *(const uint4*)(pAh + k1 + i * 8);
                aP[i + 4] = *(const uint4*)(pAl + k1 + i * 8);
            }
        }

        // ---- k16 steps 0,1 ----
        #pragma unroll
        for (int k16 = 0; k16 < 2; k16++) {
            const int acol = k16 * 16 + acolL;
            const int bcol = k16 * 16 + bcolL;
            uint32_t aH[2][4], aL[2][4], bH[4][4], bL[4][4];
            LDSM4(aH[0], sAh + (uint32_t)((arow      ) * ASTRIDE2 + acol) * 2);
            LDSM4(aH[1], sAh + (uint32_t)((arow + 16 ) * ASTRIDE2 + acol) * 2);
            LDSM4(aL[0], sAl + (uint32_t)((arow      ) * ASTRIDE2 + acol) * 2);
            LDSM4(aL[1], sAl + (uint32_t)((arow + 16 ) * ASTRIDE2 + acol) * 2);
            #pragma unroll
            for (int nt = 0; nt < 4; nt++) {
                LDSM4(bH[nt], sBh + (uint32_t)((brow + nt * 16) * ASTRIDE2 + bcol) * 2);
                LDSM4(bL[nt], sBl + (uint32_t)((brow + nt * 16) * ASTRIDE2 + bcol) * 2);
            }
            #pragma unroll
            for (int mt = 0; mt < 2; mt++)
                #pragma unroll
                for (int n8 = 0; n8 < 8; n8++) {
                    uint32_t* bh2 = &bH[n8 >> 1][(n8 & 1) * 2];
                    uint32_t* bl2 = &bL[n8 >> 1][(n8 & 1) * 2];
                    MMA16816(d[mt][n8], aH[mt], bh2);
                    MMA16816(d[mt][n8], aH[mt], bl2);
                    MMA16816(d[mt][n8], aL[mt], bh2);
                }
        }

        // ---- store A prefetch to alternate stage; B prefetch (regs) ----
        uint4 bP[8];
        if (has) {
            #pragma unroll
            for (int i = 0; i < 4; i++) {
                *(uint4*)(st + sidx + i * 8)        = aP[i];
                *(uint4*)(st + 9216 + sidx + i * 8) = aP[i + 4];
            }
            #pragma unroll
            for (int i = 0; i < 4; i++) {
                bP[i]     = *(const uint4*)(pBh + k1 + i * 8);
                bP[i + 4] = *(const uint4*)(pBl + k1 + i * 8);
            }
        }

        // ---- k16 steps 2,3 ----
        #pragma unroll
        for (int k16 = 2; k16 < 4; k16++) {
            const int acol = k16 * 16 + acolL;
            const int bcol = k16 * 16 + bcolL;
            uint32_t aH[2][4], aL[2][4], bH[4][4], bL[4][4];
            LDSM4(aH[0], sAh + (uint32_t)((arow      ) * ASTRIDE2 + acol) * 2);
            LDSM4(aH[1], sAh + (uint32_t)((arow + 16 ) * ASTRIDE2 + acol) * 2);
            LDSM4(aL[0], sAl + (uint32_t)((arow      ) * ASTRIDE2 + acol) * 2);
            LDSM4(aL[1], sAl + (uint32_t)((arow + 16 ) * ASTRIDE2 + acol) * 2);
            #pragma unroll
            for (int nt = 0; nt < 4; nt++) {
                LDSM4(bH[nt], sBh + (uint32_t)((brow + nt * 16) * ASTRIDE2 + bcol) * 2);
                LDSM4(bL[nt], sBl + (uint32_t)((brow + nt * 16) * ASTRIDE2 + bcol) * 2);
            }
            #pragma unroll
            for (int mt = 0; mt < 2; mt++)
                #pragma unroll
                for (int n8 = 0; n8 < 8; n8++) {
                    uint32_t* bh2 = &bH[n8 >> 1][(n8 & 1) * 2];
                    uint32_t* bl2 = &bL[n8 >> 1][(n8 & 1) * 2];
                    MMA16816(d[mt][n8], aH[mt], bh2);
                    MMA16816(d[mt][n8], aH[mt], bl2);
                    MMA16816(d[mt][n8], aL[mt], bh2);
                }
        }

        // ---- store B prefetch to alternate stage ----
        if (has) {
            #pragma unroll
            for (int i = 0; i < 4; i++) {
                *(uint4*)(st + 18432 + sidx + i * 8) = bP[i];
                *(uint4*)(st + 27648 + sidx + i * 8) = bP[i + 4];
            }
        }
        __syncthreads();   // single barrier per 64-deep chunk
    }

    #pragma unroll
    for (int mt = 0; mt < 2; mt++) {
        const int r0 = wm * 32 + mt * 16 + (lane >> 2);
        #pragma unroll
        for (int n8 = 0; n8 < 8; n8++) {
            const int c0 = wn * 64 + n8 * 8 + (lane & 3) * 2;
            Cs[r0 * 129 + c0]       = d[mt][n8][0];
            Cs[r0 * 129 + c0 + 1]   = d[mt][n8][1];
            Cs[(r0+8) * 129 + c0]   = d[mt][n8][2];
            Cs[(r0+8) * 129 + c0+1] = d[mt][n8][3];
        }
    }
    __syncthreads();
}

// ---------------- projection kernel (tensor cores, bf16 hi/lo outputs) ----------------
__global__ __launch_bounds__(256, 1)
void proj_mma()
{
    extern __shared__ __nv_bfloat16 sm[];
    float* Cs = (float*)sm;
    const int tid = threadIdx.x, lane = tid & 31, wid = tid >> 5;
    const int z = blockIdx.z, side = z / 3, kind = z % 3;
    const int m0 = blockIdx.y * 128, n0 = blockIdx.x * 128;

    const __nv_bfloat16* Ah = g_inh + (size_t)side * M_ * D_ + (size_t)m0 * D_;
    const __nv_bfloat16* Al = g_inl + (size_t)side * M_ * D_ + (size_t)m0 * D_;
    const __nv_bfloat16* Bh = g_wth + (size_t)z * D_ * D_ + (size_t)n0 * D_;
    const __nv_bfloat16* Bl = g_wtl + (size_t)z * D_ * D_ + (size_t)n0 * D_;

    gemm128_mma(Ah, Al, D_, Bh, Bl, D_, D_, sm, Cs);

    const int bq = m0 >> 11;
    const int s0 = m0 & 2047;

    if (kind != 2) {
        __nv_bfloat16* dh = (kind == 0) ? g_qh : g_kh;
        __nv_bfloat16* dl = (kind == 0) ? g_ql : g_kl;
        // Q pre-scaled by 1/sqrt(64) * log2(e) so flash softmax can use exp2
        const float scale = (kind == 0) ? 0.125f * 1.44269504f : 1.0f;
        #pragma unroll
        for (int rr = 0; rr < 16; rr++) {
            const int row = wid * 16 + rr;
            const int s = s0 + row;
            #pragma unroll
            for (int g = 0; g < 2; g++) {
                const int cl = g * 64 + lane * 2;
                const int n = n0 + cl;
                const int h = n >> 6, dd = (n & 63) + side * 64;
                float v0 = Cs[row * 129 + cl] * scale;
                float v1 = Cs[row * 129 + cl + 1] * scale;
                float r0, r1;
                uint32_t hh = pack_hi2(v0, v1, r0, r1);
                uint32_t ll = pack2(r0, r1);
                size_t o = ((size_t)(bq * H_ + h) * S_ + s) * DH + dd;
                *(uint32_t*)(dh + o) = hh;
                *(uint32_t*)(dl + o) = ll;
            }
        }
    } else {
        #pragma unroll
        for (int cc = 0; cc < 16; cc++) {
            const int col = wid * 16 + cc;
            const int n = n0 + col;
            const int h = n >> 6, dd = (n & 63) + side * 64;
            size_t base = ((size_t)(bq * H_ + h) * DH + dd) * S_ + s0;
            #pragma unroll
            for (int rb = 0; rb < 4; rb++) {
                const int r = rb * 32 + lane;
                float v = Cs[r * 129 + col];
                __nv_bfloat16 hh, ll;
                cvt_hilo(v, hh, ll);
                g_vth[base + r] = hh;
                g_vtl[base + r] = ll;
            }
        }
    }
}

// ---------------- output projection (tensor cores) ----------------
__global__ __launch_bounds__(256, 1)
void outproj_mma(const float* __restrict__ bias, float* __restrict__ out)
{
    extern __shared__ __nv_bfloat16 sm[];
    float* Cs = (float*)sm;
    const int tid = threadIdx.x, lane = tid & 31, wid = tid >> 5;
    const int m0 = blockIdx.y * 128, n0 = blockIdx.x * 128;
    const int K = 2048;

    const __nv_bfloat16* Ah = g_aoh + (size_t)m0 * K;
    const __nv_bfloat16* Al = g_aol + (size_t)m0 * K;
    const __nv_bfloat16* Bh = g_wpth + (size_t)n0 * K;
    const __nv_bfloat16* Bl = g_wptl + (size_t)n0 * K;

    gemm128_mma(Ah, Al, K, Bh, Bl, K, K, sm, Cs);

    #pragma unroll
    for (int rr = 0; rr < 16; rr++) {
        const int row = wid * 16 + rr;
        const size_t gm = (size_t)(m0 + row);
        #pragma unroll
        for (int g = 0; g < 4; g++) {
            const int col = g * 32 + lane;
            out[gm * D_ + n0 + col] = Cs[row * 129 + col] + bias[n0 + col];
        }
    }
}

// ---------------- flash attention with mma.sync (R8 config + exp2 softmax) ----------------
#define FQH 0
#define FQL 17408
#define FKH 34816
#define FKL 43520
#define FVH 52224
#define FVL 61440
#define FLASH_ELE 70656
#define FLASH_BYTES (FLASH_ELE*2)
#define NBLK 32

__global__ __launch_bounds__(256, 1)
void flash_mma()
{
    extern __shared__ __nv_bfloat16 fsm[];
    const uint32_t smb = smem_u32(fsm);
    const int tid = threadIdx.x, lane = tid & 31, wid = tid >> 5;
    const int bh = blockIdx.y;
    const int s0 = blockIdx.x * 128;

    const __nv_bfloat16* Qh = g_qh + (size_t)bh * S_ * DH;
    const __nv_bfloat16* Ql = g_ql + (size_t)bh * S_ * DH;
    const __nv_bfloat16* Kh = g_kh + (size_t)bh * S_ * DH;
    const __nv_bfloat16* Kl = g_kl + (size_t)bh * S_ * DH;
    const __nv_bfloat16* Vth = g_vth + (size_t)bh * DH * S_;
    const __nv_bfloat16* Vtl = g_vtl + (size_t)bh * DH * S_;

    {
        const int row = tid >> 1, c = (tid & 1) * 64;
        const __nv_bfloat16* sq = Qh + (size_t)(s0 + row) * DH + c;
        const __nv_bfloat16* sl = Ql + (size_t)(s0 + row) * DH + c;
        __nv_bfloat16* dq = fsm + FQH + row * 136 + c;
        __nv_bfloat16* dl = fsm + FQL + row * 136 + c;
        #pragma unroll
        for (int i = 0; i < 8; i++) {
            *(uint4*)(dq + i * 8) = *(const uint4*)(sq + i * 8);
            *(uint4*)(dl + i * 8) = *(const uint4*)(sl + i * 8);
        }
    }

    float O[16][4];
    #pragma unroll
    for (int i = 0; i < 16; i++)
        #pragma unroll
        for (int q = 0; q < 4; q++) O[i][q] = 0.f;
    float mrow[2] = {-1e30f, -1e30f}, lrow[2] = {0.f, 0.f};

    const int arow = wid * 16 + (lane & 15);
    const int acolL = (lane >> 4) * 8;
    const int brow = (lane & 7) + ((lane >> 1) & 8);
    const int bcolL = ((lane >> 3) & 1) * 8;

    for (int b = 0; b < NBLK; b++) {
        const int j0 = b * 64;

        {
            const int row = tid >> 2, c = (tid & 3) * 32;
            const __nv_bfloat16* sh = Kh + (size_t)(j0 + row) * DH + c;
            const __nv_bfloat16* sl = Kl + (size_t)(j0 + row) * DH + c;
            __nv_bfloat16* dh = fsm + FKH + row * 136 + c;
            __nv_bfloat16* dl = fsm + FKL + row * 136 + c;
            #pragma unroll
            for (int i = 0; i < 4; i++) {
                *(uint4*)(dh + i * 8) = *(const uint4*)(sh + i * 8);
                *(uint4*)(dl + i * 8) = *(const uint4*)(sl + i * 8);
            }
        }
        {
            const int row = tid >> 1, c = (tid & 1) * 32;
            const __nv_bfloat16* vh = Vth + (size_t)row * S_ + j0 + c;
            const __nv_bfloat16* vl = Vtl + (size_t)row * S_ + j0 + c;
            __nv_bfloat16* dh = fsm + FVH + row * 72 + c;
            __nv_bfloat16* dl = fsm + FVL + row * 72 + c;
            #pragma unroll
            for (int i = 0; i < 4; i++) {
                *(uint4*)(dh + i * 8) = *(const uint4*)(vh + i * 8);
                *(uint4*)(dl + i * 8) = *(const uint4*)(vl + i * 8);
            }
        }
        __syncthreads();

        float sv[8][4];
        #pragma unroll
        for (int j = 0; j < 8; j++)
            #pragma unroll
            for (int q = 0; q < 4; q++) sv[j][q] = 0.f;

        const uint32_t kHb = smb + (uint32_t)FKH * 2;
        const uint32_t kLb = smb + (uint32_t)FKL * 2;
        #pragma unroll
        for (int kk = 0; kk < 8; kk++) {
            const int acol = kk * 16 + acolL;
            const int bcol = kk * 16 + bcolL;
            uint32_t aH[4], aL[4], bHf[4][4], bLf[4][4];
            LDSM4(aH, smb + (uint32_t)(FQH + arow * 136 + acol) * 2);
            LDSM4(aL, smb + (uint32_t)(FQL + arow * 136 + acol) * 2);
            #pragma unroll
            for (int nt = 0; nt < 4; nt++) {
                LDSM4(bHf[nt], kHb + (uint32_t)((nt * 16 + brow) * 136 + bcol) * 2);
                LDSM4(bLf[nt], kLb + (uint32_t)((nt * 16 + brow) * 136 + bcol) * 2);
            }
            #pragma unroll
            for (int n8 = 0; n8 < 8; n8++) {
                uint32_t* bh2 = &bHf[n8 >> 1][(n8 & 1) * 2];
                uint32_t* bl2 = &bLf[n8 >> 1][(n8 & 1) * 2];
                MMA16816(sv[n8], aH, bh2);
                MMA16816(sv[n8], aH, bl2);
                MMA16816(sv[n8], aL, bh2);
            }
        }

        // scores are in log2-domain (Q pre-scaled by log2e); use exp2
        float bm0 = sv[0][0], bm1 = sv[0][2];
        #pragma unroll
        for (int j = 0; j < 8; j++) {
            bm0 = fmaxf(bm0, fmaxf(sv[j][0], sv[j][1]));
            bm1 = fmaxf(bm1, fmaxf(sv[j][2], sv[j][3]));
        }
        bm0 = fmaxf(bm0, __shfl_xor_sync(0xffffffffu, bm0, 1));
        bm0 = fmaxf(bm0, __shfl_xor_sync(0xffffffffu, bm0, 2));
        bm1 = fmaxf(bm1, __shfl_xor_sync(0xffffffffu, bm1, 1));
        bm1 = fmaxf(bm1, __shfl_xor_sync(0xffffffffu, bm1, 2));
        const float mn0 = fmaxf(mrow[0], bm0), mn1 = fmaxf(mrow[1], bm1);
        const float corr0 = exp2f(mrow[0] - mn0), corr1 = exp2f(mrow[1] - mn1);
        float bs0 = 0.f, bs1 = 0.f;
        #pragma unroll
        for (int j = 0; j < 8; j++) {
            sv[j][0] = exp2f(sv[j][0] - mn0);
            sv[j][1] = exp2f(sv[j][1] - mn0);
            sv[j][2] = exp2f(sv[j][2] - mn1);
            sv[j][3] = exp2f(sv[j][3] - mn1);
            bs0 += sv[j][0] + sv[j][1];
            bs1 += sv[j][2] + sv[j][3];
        }
        bs0 += __shfl_xor_sync(0xffffffffu, bs0, 1);
        bs0 += __shfl_xor_sync(0xffffffffu, bs0, 2);
        bs1 += __shfl_xor_sync(0xffffffffu, bs1, 1);
        bs1 += __shfl_xor_sync(0xffffffffu, bs1, 2);
        lrow[0] = lrow[0] * corr0 + bs0;
        lrow[1] = lrow[1] * corr1 + bs1;
        mrow[0] = mn0; mrow[1] = mn1;
        #pragma unroll
        for (int i = 0; i < 16; i++) {
            O[i][0] *= corr0; O[i][1] *= corr0;
            O[i][2] *= corr1; O[i][3] *= corr1;
        }

        const uint32_t vHb = smb + (uint32_t)FVH * 2;
        const uint32_t vLb = smb + (uint32_t)FVL * 2;
        #pragma unroll
        for (int c = 0; c < 4; c++) {
            float r0, r1;
            uint32_t pah[4], pal[4];
            pah[0] = pack_hi2(sv[2*c][0],   sv[2*c][1],   r0, r1); pal[0] = pack2(r0, r1);
            pah[1] = pack_hi2(sv[2*c][2],   sv[2*c][3],   r0, r1); pal[1] = pack2(r0, r1);
            pah[2] = pack_hi2(sv[2*c+1][0], sv[2*c+1][1], r0, r1); pal[2] = pack2(r0, r1);
            pah[3] = pack_hi2(sv[2*c+1][2], sv[2*c+1][3], r0, r1); pal[3] = pack2(r0, r1);
            const int bcol = c * 16 + bcolL;
            #pragma unroll
            for (int t = 0; t < 8; t++) {
                uint32_t vh[4], vl[4];
                LDSM4(vh, vHb + (uint32_t)((t * 16 + brow) * 72 + bcol) * 2);
                LDSM4(vl, vLb + (uint32_t)((t * 16 + brow) * 72 + bcol) * 2);
                #pragma unroll
                for (int h2 = 0; h2 < 2; h2++) {
                    uint32_t* vh2 = &vh[h2 * 2];
                    uint32_t* vl2 = &vl[h2 * 2];
                    MMA16816(O[t * 2 + h2], pah, vh2);
                    MMA16816(O[t * 2 + h2], pah, vl2);
                    MMA16816(O[t * 2 + h2], pal, vh2);
                }
            }
        }
        __syncthreads();
    }

    const int b = bh / H_, h = bh % H_;
    const float inv0 = 1.0f / lrow[0], inv1 = 1.0f / lrow[1];
    size_t base0 = (size_t)(b * S_ + s0 + wid * 16 + (lane >> 2)) * 2048 + (size_t)h * 128;
    size_t base1 = base0 + (size_t)8 * 2048;
    #pragma unroll
    for (int n8 = 0; n8 < 16; n8++) {
        const int dv = n8 * 8 + (lane & 3) * 2;
        float v0 = O[n8][0] * inv0, v1 = O[n8][1] * inv0;
        float v2 = O[n8][2] * inv1, v3 = O[n8][3] * inv1;
        float r0, r1;
        uint32_t hh = pack_hi2(v0, v1, r0, r1);
        *(uint32_t*)(g_aoh + base0 + dv) = hh;
        *(uint32_t*)(g_aol + base0 + dv) = pack2(r0, r1);
        hh = pack_hi2(v2, v3, r0, r1);
        *(uint32_t*)(g_aoh + base1 + dv) = hh;
        *(uint32_t*)(g_aol + base1 + dv) = pack2(r0, r1);
    }
}

// =================================================================
extern "C" void kernel_launch(void* const* d_in, const int* in_sizes, int n_in,
                              void* d_out, int out_size)
{
    const float* x    = (const float*)d_in[0];
    const float* c    = (const float*)d_in[1];
    const float* Wp   = (const float*)d_in[8];
    const float* bias = (const float*)d_in[9];
    float* out = (float*)d_out;

    cudaFuncSetAttribute(proj_mma, cudaFuncAttributeMaxDynamicSharedMemorySize, DSMEM_BYTES);
    cudaFuncSetAttribute(outproj_mma, cudaFuncAttributeMaxDynamicSharedMemorySize, DSMEM_BYTES);
    cudaFuncSetAttribute(flash_mma, cudaFuncAttributeMaxDynamicSharedMemorySize, FLASH_BYTES);

    void *p_wpth, *p_wptl;
    cudaGetSymbolAddress(&p_wpth, g_wpth);
    cudaGetSymbolAddress(&p_wptl, g_wptl);

    conv_in<<<dim3(M_*D_/4/256, 2), 256>>>(x, c);
    transpose_conv6<<<dim3(32, 32, 6), dim3(32, 8)>>>(
        (const float*)d_in[2], (const float*)d_in[3], (const float*)d_in[4],
        (const float*)d_in[5], (const float*)d_in[6], (const float*)d_in[7]);
    transpose_conv<<<dim3(32, 64), dim3(32, 8)>>>(
        Wp, (__nv_bfloat16*)p_wpth, (__nv_bfloat16*)p_wptl, 2048, D_);

    proj_mma<<<dim3(8, 64, 6), 256, DSMEM_BYTES>>>();

    flash_mma<<<dim3(S_/128, B_*H_), 256, FLASH_BYTES>>>();

    outproj_mma<<<dim3(8, 64), 256, DSMEM_BYTES>>>(bias, out);
}